// round 14
// baseline (speedup 1.0000x reference)
#include <cuda_runtime.h>
#include <cstdint>
#include <math.h>

#define COL 14
#define NJ 23
#define PAIR_ELEMS (COL * COL)   // 196
#define WARPS_PER_BLOCK 8
#define BLOCK_THREADS (WARPS_PER_BLOCK * 32)
#define CHUNK 10                 // 94208/(8*10) -> 1178 blocks ~ one wave

struct Tables {
    float M[PAIR_ELEMS];         // [i*COL + r] = M[r][i]  (column i contiguous)
    float cmin[COL], cmax[COL], s1[COL], s2[COL];
};

__device__ float        g_sum   = 0.0f;
__device__ unsigned int g_count = 0u;

// ---- packed f32x2 helpers (sm_103a FFMA2/FMUL2/FADD2 via PTX) ----
__device__ __forceinline__ unsigned long long pk2(float a, float b) {
    unsigned long long r;
    asm("mov.b64 %0, {%1, %2};" : "=l"(r) : "f"(a), "f"(b));
    return r;
}
__device__ __forceinline__ void fma2(unsigned long long& d,
                                     unsigned long long a, unsigned long long b) {
    asm("fma.rn.f32x2 %0, %1, %2, %0;" : "+l"(d) : "l"(a), "l"(b));
}
__device__ __forceinline__ void add2(unsigned long long& d, unsigned long long a) {
    asm("add.rn.f32x2 %0, %1, %0;" : "+l"(d) : "l"(a));
}
__device__ __forceinline__ unsigned long long mul2(unsigned long long a,
                                                   unsigned long long b) {
    unsigned long long r;
    asm("mul.rn.f32x2 %0, %1, %2;" : "=l"(r) : "l"(a), "l"(b));
    return r;
}
__device__ __forceinline__ float2 upk2(unsigned long long p) {
    float2 f;
    asm("mov.b64 {%0, %1}, %2;" : "=f"(f.x), "=f"(f.y) : "l"(p));
    return f;
}

__device__ __forceinline__ void amax_node(float& v, int& i, float vr, int ir) {
    if (vr > v) { v = vr; i = ir; }   // strict >: ties keep smaller index
}
__device__ __forceinline__ void prefetch_l1(const void* p) {
    asm volatile("prefetch.global.L1 [%0];" :: "l"(p));
}

__global__ __launch_bounds__(BLOCK_THREADS, 8)
void mse3d_kernel(const float* __restrict__ o,
                  const float* __restrict__ h,
                  const float* __restrict__ t,
                  const int*   __restrict__ v,
                  float* __restrict__ out,
                  int n_pairs, int nblocks, Tables tb) {
    __shared__ __align__(16) float sMt[PAIR_ELEMS];
    __shared__ float sColMin[COL], sColMax[COL];
    __shared__ float sColS1[COL], sColS2[COL];
    __shared__ float wsum[WARPS_PER_BLOCK];

    const int tid = threadIdx.x;

    // ---- copy precomputed tables from param (constant bank) to smem ----
    if (tid < PAIR_ELEMS) sMt[tid] = tb.M[tid];
    if (tid >= PAIR_ELEMS && tid < PAIR_ELEMS + COL) {
        const int i = tid - PAIR_ELEMS;
        sColMin[i] = tb.cmin[i];
        sColMax[i] = tb.cmax[i];
        sColS1[i]  = tb.s1[i];
        sColS2[i]  = tb.s2[i];
    }
    __syncthreads();

    const int lane  = tid & 31;
    const int warp  = tid >> 5;
    const int gwarp = blockIdx.x * WARPS_PER_BLOCK + warp;
    const int pair0 = gwarp * CHUNK;
    const int cnt   = min(CHUNK, n_pairs - pair0);

    float acc  = 0.0f;                 // scalar d1 cross terms
    float acc2 = 0.0f;                 // d2 + per-pair constants
    unsigned long long accp = 0ull;    // packed sum of h^2

    if (cnt > 0) {
        const bool hasb = (lane < 17);     // second float4 (idx 32+lane < 49)

        // per-lane sub-pair coordinates (each (q,q+1) shares a row; c even)
        const int ea  = 4 * lane;
        const int r0a = ea / COL,       c0a = ea - r0a * COL;
        const int r1a = (ea + 2) / COL, c1a = (ea + 2) - r1a * COL;
        const int eb  = 4 * (32 + lane);
        const int r0b = eb / COL,       c0b = eb - r0b * COL;
        const int r1b = (eb + 2) / COL, c1b = (eb + 2) - r1b * COL;

        const float4* hbase = (const float4*)(h + (size_t)pair0 * PAIR_ELEMS);

        // per-chunk t/v prefetch (coalesced), broadcast via shuffle
        const float tl = (lane < 3 * cnt) ? t[(size_t)pair0 * 3 + lane] : 0.0f;
        const int   vl = (lane < cnt) ? v[(size_t)(pair0 + lane) * 2] : 0;

        // warm L1 for pair 0
        prefetch_l1(hbase + lane);
        if (hasb) prefetch_l1(hbase + 32 + lane);

        int myAmax = 0;   // lane k banks pair k's argmax

        for (int k = 0; k < cnt; k++) {
            const float4* hp = hbase + (size_t)k * 49;
            float4 va = hp[lane];
            float4 vb = hasb ? hp[32 + lane] : make_float4(0.f, 0.f, 0.f, 0.f);

            // prefetch next pair's tile into L1 (zero-register pipelining)
            if (k + 1 < cnt) {
                prefetch_l1(hp + 49 + lane);
                if (hasb) prefetch_l1(hp + 49 + 32 + lane);
            }

            // per-pair scalars via shuffle (no memory)
            const float t0 = __shfl_sync(0xffffffffu, tl, 3 * k);
            const float t1 = __shfl_sync(0xffffffffu, tl, 3 * k + 1);
            const int   vv = __shfl_sync(0xffffffffu, vl, k);

            // ---- tree argmax over the 8 local elements ----
            float m0 = va.x; int i0 = ea;
            amax_node(m0, i0, va.y, ea + 1);
            float m1 = va.z; int i1 = ea + 2;
            amax_node(m1, i1, va.w, ea + 3);
            float m2 = vb.x; int i2 = eb;
            amax_node(m2, i2, vb.y, eb + 1);
            float m3 = vb.z; int i3 = eb + 2;
            amax_node(m3, i3, vb.w, eb + 3);
            amax_node(m0, i0, m1, i1);
            amax_node(m2, i2, m3, i3);
            amax_node(m0, i0, m2, i2);
            // h >= 0: bits order-isomorphic; first occurrence via min-index
            const unsigned int bbits = __float_as_uint(m0);
            const unsigned int mbits = __reduce_max_sync(0xffffffffu, bbits);
            const int amax = (int)__reduce_min_sync(
                0xffffffffu, (bbits == mbits) ? (unsigned)i0 : 0xffffffffu);
            if (lane == k) myAmax = amax;

            // packed h values (reused for h^2 and masked path)
            const unsigned long long pa01 = pk2(va.x, va.y);
            const unsigned long long pa23 = pk2(va.z, va.w);
            const unsigned long long pb01 = pk2(vb.x, vb.y);
            const unsigned long long pb23 = pk2(vb.z, vb.w);

            // ---- always: sum h^2 (packed) ----
            fma2(accp, pa01, pa01);
            fma2(accp, pa23, pa23);
            fma2(accp, pb01, pb01);   // zeros when !hasb
            fma2(accp, pb23, pb23);

            // ---- mask / normalization ----
            const int xi = (int)truncf(t0 * (float)COL);
            const int yi = (int)truncf(t1 * (float)COL);
            const bool in_range = (xi >= 0) && (xi <= COL - 1) &&
                                  (yi >= 0) && (yi <= COL - 1);
            const bool mask = (vv == 1) && in_range;

            if (mask) {
                // d1_pair = sum h^2 - 2*sum(h*tt) + sum(tt^2)
                const int xc = min(max(xi, 0), COL - 1);
                const int yc = min(max(yi, 0), COL - 1);
                const float mn  = sColMin[yc] * sColMin[xc];
                const float mx  = sColMax[yc] * sColMax[xc];
                const float inv = 1.0f / (mx - mn);
                const float nb  = -mn * inv;
                const float* gy = &sMt[yc * COL];
                const float* gx = &sMt[xc * COL];

                unsigned long long hw2 = 0ull, sh2 = 0ull;
                {
                    const float2 g0 = *(const float2*)(gx + c0a);  // aligned: c even
                    const float2 g1 = *(const float2*)(gx + c1a);
                    const float gy0 = gy[r0a], gy1 = gy[r1a];
                    fma2(hw2, pa01, mul2(pk2(gy0, gy0), pk2(g0.x, g0.y)));
                    fma2(hw2, pa23, mul2(pk2(gy1, gy1), pk2(g1.x, g1.y)));
                    add2(sh2, pa01);
                    add2(sh2, pa23);
                }
                if (hasb) {
                    const float2 g0 = *(const float2*)(gx + c0b);
                    const float2 g1 = *(const float2*)(gx + c1b);
                    const float gy0 = gy[r0b], gy1 = gy[r1b];
                    fma2(hw2, pb01, mul2(pk2(gy0, gy0), pk2(g0.x, g0.y)));
                    fma2(hw2, pb23, mul2(pk2(gy1, gy1), pk2(g1.x, g1.y)));
                    add2(sh2, pb01);
                    add2(sh2, pb23);
                }
                const float2 hwf = upk2(hw2);
                const float2 shf = upk2(sh2);
                const float hw = hwf.x + hwf.y;
                const float sh = shf.x + shf.y;
                acc = fmaf(-2.0f * inv, hw, acc);
                acc = fmaf(-2.0f * nb,  sh, acc);
                if (lane == 0) {
                    const float S1 = sColS1[yc] * sColS1[xc];
                    const float S2 = sColS2[yc] * sColS2[xc];
                    float ct = inv * inv * S2;
                    ct = fmaf(2.0f * inv * nb, S1, ct);
                    ct = fmaf((float)PAIR_ELEMS * nb, nb, ct);
                    acc2 += ct;
                }
            }
        }

        // ====== Phase 2: all o-gathers at once (up to 30 concurrent) ======
        {
            const int kq = min(lane / 3, cnt - 1);     // clamped for shfl
            const int am = __shfl_sync(0xffffffffu, myAmax, kq);
            if (lane < 3 * cnt) {
                const int k    = lane / 3;
                const int comp = lane - 3 * k;
                const int pair = pair0 + k;
                const int b    = pair / NJ;
                const int j    = pair - b * NJ;
                const int ayk  = am / COL;
                const int axk  = am - ayk * COL;
                const int row  = b * (3 * NJ) + j + comp * NJ;
                const float ov = __ldg(o + ((size_t)row * PAIR_ELEMS + am));
                const float scale = 1.0f / (float)COL;
                const float addv = (comp == 0) ? (float)axk * scale
                                 : ((comp == 1) ? (float)ayk * scale : 0.0f);
                const float d = ov + addv - tl;        // tl == t[pair*3+comp]
                acc2 = fmaf(d, d, acc2);
            }
        }
    }

    {
        const float2 ap = upk2(accp);
        acc += ap.x + ap.y + acc2;
    }

    // ---- block reduction ----
    #pragma unroll
    for (int off = 16; off > 0; off >>= 1)
        acc += __shfl_down_sync(0xffffffffu, acc, off);
    if (lane == 0) wsum[warp] = acc;
    __syncthreads();

    if (warp == 0) {
        float s = (lane < WARPS_PER_BLOCK) ? wsum[lane] : 0.0f;
        #pragma unroll
        for (int off = WARPS_PER_BLOCK / 2; off > 0; off >>= 1)
            s += __shfl_down_sync(0xffffffffu, s, off);
        if (lane == 0) {
            atomicAdd(&g_sum, s * (1.0f / (float)NJ));
            __threadfence();
            unsigned int done = atomicAdd(&g_count, 1u);
            if (done == (unsigned)nblocks - 1) {
                float total = atomicExch(&g_sum, 0.0f);
                out[0] = total;
                g_count = 0u;
                __threadfence();
            }
        }
    }
}

extern "C" void kernel_launch(void* const* d_in, const int* in_sizes, int n_in,
                              void* d_out, int out_size) {
    const float* o = (const float*)d_in[0];
    const float* h = (const float*)d_in[1];
    const float* t = (const float*)d_in[2];
    const int*   v = (const int*)d_in[3];
    float* out = (float*)d_out;

    // ---- host-side table build (matches reference: double weights ->
    //      f32 cast -> f32 accumulation in k order) ----
    Tables tb;
    {
        double wd[9], s = 0.0;
        for (int k = 0; k < 9; k++) {
            double x = (double)(k - 4);
            wd[k] = exp(-0.5 * x * x);
            s += wd[k];
        }
        float wf[9];
        for (int k = 0; k < 9; k++) wf[k] = (float)(wd[k] / s);

        float M[COL][COL] = {};
        for (int outr = 0; outr < COL; outr++)
            for (int k = -4; k <= 4; k++) {
                int ii = (outr + k + 2 * COL) % (2 * COL);
                if (ii >= COL) ii = 2 * COL - 1 - ii;
                M[outr][ii] += wf[k + 4];
            }
        for (int i = 0; i < COL; i++) {
            float mn = INFINITY, mx = -INFINITY, s1 = 0.0f, s2 = 0.0f;
            for (int r = 0; r < COL; r++) {
                const float val = M[r][i];
                tb.M[i * COL + r] = val;   // column-major (sMt layout)
                mn = fminf(mn, val);
                mx = fmaxf(mx, val);
                s1 += val;
                s2 = fmaf(val, val, s2);
            }
            tb.cmin[i] = mn;
            tb.cmax[i] = mx;
            tb.s1[i]   = s1;
            tb.s2[i]   = s2;
        }
    }

    const int n_pairs = in_sizes[1] / PAIR_ELEMS;   // B * NJ from h
    const int pairs_per_block = WARPS_PER_BLOCK * CHUNK;
    const int blocks = (n_pairs + pairs_per_block - 1) / pairs_per_block;

    mse3d_kernel<<<blocks, BLOCK_THREADS>>>(o, h, t, v, out,
                                            n_pairs, blocks, tb);
}

// round 15
// speedup vs baseline: 1.0205x; 1.0205x over previous
#include <cuda_runtime.h>
#include <cstdint>
#include <math.h>

#define COL 14
#define NJ 23
#define PAIR_ELEMS (COL * COL)   // 196
#define WARPS_PER_BLOCK 8
#define BLOCK_THREADS (WARPS_PER_BLOCK * 32)
#define CHUNK 10                 // 94208/(8*10) -> 1178 blocks ~ one wave

__device__ float        g_sum   = 0.0f;
__device__ unsigned int g_count = 0u;

// gaussian weights exp(-k^2/2)/sum, k=-4..4 (normalized in double, cast to f32)
__device__ __constant__ float c_w[9] = {
    0.000133832f, 0.00443186f, 0.05399111f, 0.24197140f, 0.39894345f,
    0.24197140f, 0.05399111f, 0.00443186f, 0.000133832f
};

// ---- packed f32x2 helpers ----
__device__ __forceinline__ unsigned long long pk2(float a, float b) {
    unsigned long long r;
    asm("mov.b64 %0, {%1, %2};" : "=l"(r) : "f"(a), "f"(b));
    return r;
}
__device__ __forceinline__ void fma2(unsigned long long& d,
                                     unsigned long long a, unsigned long long b) {
    asm("fma.rn.f32x2 %0, %1, %2, %0;" : "+l"(d) : "l"(a), "l"(b));
}
__device__ __forceinline__ void add2(unsigned long long& d, unsigned long long a) {
    asm("add.rn.f32x2 %0, %1, %0;" : "+l"(d) : "l"(a));
}
__device__ __forceinline__ unsigned long long mul2(unsigned long long a,
                                                   unsigned long long b) {
    unsigned long long r;
    asm("mul.rn.f32x2 %0, %1, %2;" : "=l"(r) : "l"(a), "l"(b));
    return r;
}
__device__ __forceinline__ float2 upk2(unsigned long long p) {
    float2 f;
    asm("mov.b64 {%0, %1}, %2;" : "=f"(f.x), "=f"(f.y) : "l"(p));
    return f;
}

__device__ __forceinline__ void amax_node(float& v, int& i, float vr, int ir) {
    if (vr > v) { v = vr; i = ir; }   // strict >: ties keep smaller index
}
__device__ __forceinline__ void prefetch_l1(const void* p) {
    asm volatile("prefetch.global.L1 [%0];" :: "l"(p));
}

__global__ __launch_bounds__(BLOCK_THREADS, 6)
void mse3d_kernel(const float* __restrict__ o,
                  const float* __restrict__ h,
                  const float* __restrict__ t,
                  const int*   __restrict__ v,
                  float* __restrict__ out,
                  int n_pairs, int nblocks) {
    __shared__ __align__(16) float sMt[PAIR_ELEMS];   // [i*COL+r] = M[r][i]
    __shared__ float sColMin[COL], sColMax[COL];
    __shared__ float sColS1[COL], sColS2[COL];
    __shared__ float wsum[WARPS_PER_BLOCK];

    const int tid = threadIdx.x;

    // ---- per-block gaussian matrix build (hardcoded weights) ----
    if (tid < PAIR_ELEMS) {
        const int outr = tid / COL;
        const int i    = tid % COL;
        float m = 0.0f;
        #pragma unroll
        for (int k = -4; k <= 4; k++) {
            int ii = (outr + k + 2 * COL) % (2 * COL);
            if (ii >= COL) ii = 2 * COL - 1 - ii;
            if (ii == i) m += c_w[k + 4];
        }
        sMt[i * COL + outr] = m;
    }
    __syncthreads();
    if (tid < COL) {
        float mn = INFINITY, mx = -INFINITY, s1 = 0.0f, s2 = 0.0f;
        #pragma unroll
        for (int r = 0; r < COL; r++) {
            float val = sMt[tid * COL + r];   // M[r][tid]
            mn = fminf(mn, val);
            mx = fmaxf(mx, val);
            s1 += val;
            s2 = fmaf(val, val, s2);
        }
        sColMin[tid] = mn;
        sColMax[tid] = mx;
        sColS1[tid]  = s1;
        sColS2[tid]  = s2;
    }
    __syncthreads();

    const int lane  = tid & 31;
    const int warp  = tid >> 5;
    const int gwarp = blockIdx.x * WARPS_PER_BLOCK + warp;
    const int pair0 = gwarp * CHUNK;
    const int cnt   = min(CHUNK, n_pairs - pair0);

    float acc  = 0.0f;                 // scalar d1 cross terms
    float acc2 = 0.0f;                 // d2 + per-pair constants
    unsigned long long accp = 0ull;    // packed sum of h^2

    if (cnt > 0) {
        const bool hasb = (lane < 17);     // second float4 (idx 32+lane < 49)

        // per-lane sub-pair coordinates (each (q,q+1) shares a row; c even)
        const int ea  = 4 * lane;
        const int r0a = ea / COL,       c0a = ea - r0a * COL;
        const int r1a = (ea + 2) / COL, c1a = (ea + 2) - r1a * COL;
        const int eb  = 4 * (32 + lane);
        const int r0b = eb / COL,       c0b = eb - r0b * COL;
        const int r1b = (eb + 2) / COL, c1b = (eb + 2) - r1b * COL;

        const float4* hbase = (const float4*)(h + (size_t)pair0 * PAIR_ELEMS);

        // per-chunk t/v prefetch (coalesced), broadcast via shuffle
        const float tl = (lane < 3 * cnt) ? t[(size_t)pair0 * 3 + lane] : 0.0f;
        const int   vl = (lane < cnt) ? v[(size_t)(pair0 + lane) * 2] : 0;

        // warm L1 for pairs 0,1
        prefetch_l1(hbase + lane);
        if (hasb) prefetch_l1(hbase + 32 + lane);
        if (cnt > 1) {
            prefetch_l1(hbase + 49 + lane);
            if (hasb) prefetch_l1(hbase + 49 + 32 + lane);
        }

        int myAmax = 0;   // lane k banks pair k's argmax (disjoint lanes A/B)

        // ============ 2-pair interleaved main loop (MLP x2) ============
        for (int k = 0; k < cnt; k += 2) {
            const bool hasB2 = (k + 1 < cnt);
            const float4* hpA = hbase + (size_t)k * 49;
            const float4* hpB = hpA + 49;

            // ---- 4 independent LDG.128 issued before any consumption ----
            float4 vaA = hpA[lane];
            float4 vbA = hasb ? hpA[32 + lane] : make_float4(0.f, 0.f, 0.f, 0.f);
            float4 vaB = hasB2 ? hpB[lane] : make_float4(0.f, 0.f, 0.f, 0.f);
            float4 vbB = (hasB2 && hasb) ? hpB[32 + lane]
                                         : make_float4(0.f, 0.f, 0.f, 0.f);

            // prefetch pairs k+2, k+3
            if (k + 2 < cnt) {
                prefetch_l1(hpA + 98 + lane);
                if (hasb) prefetch_l1(hpA + 98 + 32 + lane);
            }
            if (k + 3 < cnt) {
                prefetch_l1(hpA + 147 + lane);
                if (hasb) prefetch_l1(hpA + 147 + 32 + lane);
            }

            // ---- per-pair scalars via shuffle ----
            const float t0A = __shfl_sync(0xffffffffu, tl, 3 * k);
            const float t1A = __shfl_sync(0xffffffffu, tl, 3 * k + 1);
            const int   vvA = __shfl_sync(0xffffffffu, vl, k);
            const float t0B = __shfl_sync(0xffffffffu, tl, 3 * k + 3);
            const float t1B = __shfl_sync(0xffffffffu, tl, 3 * k + 4);
            const int   vvB = hasB2 ? __shfl_sync(0xffffffffu, vl, k + 1) : 0;

            // ---- argmax A ----
            {
                float m0 = vaA.x; int i0 = ea;
                amax_node(m0, i0, vaA.y, ea + 1);
                float m1 = vaA.z; int i1 = ea + 2;
                amax_node(m1, i1, vaA.w, ea + 3);
                float m2 = vbA.x; int i2 = eb;
                amax_node(m2, i2, vbA.y, eb + 1);
                float m3 = vbA.z; int i3 = eb + 2;
                amax_node(m3, i3, vbA.w, eb + 3);
                amax_node(m0, i0, m1, i1);
                amax_node(m2, i2, m3, i3);
                amax_node(m0, i0, m2, i2);
                const unsigned int bbits = __float_as_uint(m0);
                const unsigned int mbits = __reduce_max_sync(0xffffffffu, bbits);
                const int am = (int)__reduce_min_sync(
                    0xffffffffu, (bbits == mbits) ? (unsigned)i0 : 0xffffffffu);
                if (lane == k) myAmax = am;
            }
            // ---- argmax B ----
            if (hasB2) {
                float m0 = vaB.x; int i0 = ea;
                amax_node(m0, i0, vaB.y, ea + 1);
                float m1 = vaB.z; int i1 = ea + 2;
                amax_node(m1, i1, vaB.w, ea + 3);
                float m2 = vbB.x; int i2 = eb;
                amax_node(m2, i2, vbB.y, eb + 1);
                float m3 = vbB.z; int i3 = eb + 2;
                amax_node(m3, i3, vbB.w, eb + 3);
                amax_node(m0, i0, m1, i1);
                amax_node(m2, i2, m3, i3);
                amax_node(m0, i0, m2, i2);
                const unsigned int bbits = __float_as_uint(m0);
                const unsigned int mbits = __reduce_max_sync(0xffffffffu, bbits);
                const int am = (int)__reduce_min_sync(
                    0xffffffffu, (bbits == mbits) ? (unsigned)i0 : 0xffffffffu);
                if (lane == k + 1) myAmax = am;
            }

            // packed h values
            const unsigned long long pa01A = pk2(vaA.x, vaA.y);
            const unsigned long long pa23A = pk2(vaA.z, vaA.w);
            const unsigned long long pb01A = pk2(vbA.x, vbA.y);
            const unsigned long long pb23A = pk2(vbA.z, vbA.w);
            const unsigned long long pa01B = pk2(vaB.x, vaB.y);
            const unsigned long long pa23B = pk2(vaB.z, vaB.w);
            const unsigned long long pb01B = pk2(vbB.x, vbB.y);
            const unsigned long long pb23B = pk2(vbB.z, vbB.w);

            // ---- sum h^2 (packed), both pairs ----
            fma2(accp, pa01A, pa01A);
            fma2(accp, pa23A, pa23A);
            fma2(accp, pb01A, pb01A);
            fma2(accp, pb23A, pb23A);
            fma2(accp, pa01B, pa01B);   // zeros for phantom pair
            fma2(accp, pa23B, pa23B);
            fma2(accp, pb01B, pb01B);
            fma2(accp, pb23B, pb23B);

            // ---- masked path, pair A ----
            {
                const int xi = (int)truncf(t0A * (float)COL);
                const int yi = (int)truncf(t1A * (float)COL);
                const bool mask = (vvA == 1) && (xi >= 0) && (xi <= COL - 1) &&
                                  (yi >= 0) && (yi <= COL - 1);
                if (mask) {
                    const int xc = min(max(xi, 0), COL - 1);
                    const int yc = min(max(yi, 0), COL - 1);
                    const float mn  = sColMin[yc] * sColMin[xc];
                    const float mx  = sColMax[yc] * sColMax[xc];
                    const float inv = 1.0f / (mx - mn);
                    const float nb  = -mn * inv;
                    const float* gy = &sMt[yc * COL];
                    const float* gx = &sMt[xc * COL];

                    unsigned long long hw2 = 0ull, sh2 = 0ull;
                    {
                        const float2 g0 = *(const float2*)(gx + c0a);
                        const float2 g1 = *(const float2*)(gx + c1a);
                        const float gy0 = gy[r0a], gy1 = gy[r1a];
                        fma2(hw2, pa01A, mul2(pk2(gy0, gy0), pk2(g0.x, g0.y)));
                        fma2(hw2, pa23A, mul2(pk2(gy1, gy1), pk2(g1.x, g1.y)));
                        add2(sh2, pa01A);
                        add2(sh2, pa23A);
                    }
                    if (hasb) {
                        const float2 g0 = *(const float2*)(gx + c0b);
                        const float2 g1 = *(const float2*)(gx + c1b);
                        const float gy0 = gy[r0b], gy1 = gy[r1b];
                        fma2(hw2, pb01A, mul2(pk2(gy0, gy0), pk2(g0.x, g0.y)));
                        fma2(hw2, pb23A, mul2(pk2(gy1, gy1), pk2(g1.x, g1.y)));
                        add2(sh2, pb01A);
                        add2(sh2, pb23A);
                    }
                    const float2 hwf = upk2(hw2);
                    const float2 shf = upk2(sh2);
                    acc = fmaf(-2.0f * inv, hwf.x + hwf.y, acc);
                    acc = fmaf(-2.0f * nb,  shf.x + shf.y, acc);
                    if (lane == 0) {
                        const float S1 = sColS1[yc] * sColS1[xc];
                        const float S2 = sColS2[yc] * sColS2[xc];
                        float ct = inv * inv * S2;
                        ct = fmaf(2.0f * inv * nb, S1, ct);
                        ct = fmaf((float)PAIR_ELEMS * nb, nb, ct);
                        acc2 += ct;
                    }
                }
            }
            // ---- masked path, pair B ----
            {
                const int xi = (int)truncf(t0B * (float)COL);
                const int yi = (int)truncf(t1B * (float)COL);
                const bool mask = (vvB == 1) && (xi >= 0) && (xi <= COL - 1) &&
                                  (yi >= 0) && (yi <= COL - 1);
                if (mask) {
                    const int xc = min(max(xi, 0), COL - 1);
                    const int yc = min(max(yi, 0), COL - 1);
                    const float mn  = sColMin[yc] * sColMin[xc];
                    const float mx  = sColMax[yc] * sColMax[xc];
                    const float inv = 1.0f / (mx - mn);
                    const float nb  = -mn * inv;
                    const float* gy = &sMt[yc * COL];
                    const float* gx = &sMt[xc * COL];

                    unsigned long long hw2 = 0ull, sh2 = 0ull;
                    {
                        const float2 g0 = *(const float2*)(gx + c0a);
                        const float2 g1 = *(const float2*)(gx + c1a);
                        const float gy0 = gy[r0a], gy1 = gy[r1a];
                        fma2(hw2, pa01B, mul2(pk2(gy0, gy0), pk2(g0.x, g0.y)));
                        fma2(hw2, pa23B, mul2(pk2(gy1, gy1), pk2(g1.x, g1.y)));
                        add2(sh2, pa01B);
                        add2(sh2, pa23B);
                    }
                    if (hasb) {
                        const float2 g0 = *(const float2*)(gx + c0b);
                        const float2 g1 = *(const float2*)(gx + c1b);
                        const float gy0 = gy[r0b], gy1 = gy[r1b];
                        fma2(hw2, pb01B, mul2(pk2(gy0, gy0), pk2(g0.x, g0.y)));
                        fma2(hw2, pb23B, mul2(pk2(gy1, gy1), pk2(g1.x, g1.y)));
                        add2(sh2, pb01B);
                        add2(sh2, pb23B);
                    }
                    const float2 hwf = upk2(hw2);
                    const float2 shf = upk2(sh2);
                    acc = fmaf(-2.0f * inv, hwf.x + hwf.y, acc);
                    acc = fmaf(-2.0f * nb,  shf.x + shf.y, acc);
                    if (lane == 0) {
                        const float S1 = sColS1[yc] * sColS1[xc];
                        const float S2 = sColS2[yc] * sColS2[xc];
                        float ct = inv * inv * S2;
                        ct = fmaf(2.0f * inv * nb, S1, ct);
                        ct = fmaf((float)PAIR_ELEMS * nb, nb, ct);
                        acc2 += ct;
                    }
                }
            }
        }

        // ====== Phase 2: all o-gathers at once (up to 30 concurrent) ======
        {
            const int kq = min(lane / 3, cnt - 1);     // clamped for shfl
            const int am = __shfl_sync(0xffffffffu, myAmax, kq);
            if (lane < 3 * cnt) {
                const int k    = lane / 3;
                const int comp = lane - 3 * k;
                const int pair = pair0 + k;
                const int b    = pair / NJ;
                const int j    = pair - b * NJ;
                const int ayk  = am / COL;
                const int axk  = am - ayk * COL;
                const int row  = b * (3 * NJ) + j + comp * NJ;
                const float ov = __ldg(o + ((size_t)row * PAIR_ELEMS + am));
                const float scale = 1.0f / (float)COL;
                const float addv = (comp == 0) ? (float)axk * scale
                                 : ((comp == 1) ? (float)ayk * scale : 0.0f);
                const float d = ov + addv - tl;        // tl == t[pair*3+comp]
                acc2 = fmaf(d, d, acc2);
            }
        }
    }

    {
        const float2 ap = upk2(accp);
        acc += ap.x + ap.y + acc2;
    }

    // ---- block reduction ----
    #pragma unroll
    for (int off = 16; off > 0; off >>= 1)
        acc += __shfl_down_sync(0xffffffffu, acc, off);
    if (lane == 0) wsum[warp] = acc;
    __syncthreads();

    if (warp == 0) {
        float s = (lane < WARPS_PER_BLOCK) ? wsum[lane] : 0.0f;
        #pragma unroll
        for (int off = WARPS_PER_BLOCK / 2; off > 0; off >>= 1)
            s += __shfl_down_sync(0xffffffffu, s, off);
        if (lane == 0) {
            atomicAdd(&g_sum, s * (1.0f / (float)NJ));
            __threadfence();
            unsigned int done = atomicAdd(&g_count, 1u);
            if (done == (unsigned)nblocks - 1) {
                float total = atomicExch(&g_sum, 0.0f);
                out[0] = total;
                g_count = 0u;
                __threadfence();
            }
        }
    }
}

extern "C" void kernel_launch(void* const* d_in, const int* in_sizes, int n_in,
                              void* d_out, int out_size) {
    const float* o = (const float*)d_in[0];
    const float* h = (const float*)d_in[1];
    const float* t = (const float*)d_in[2];
    const int*   v = (const int*)d_in[3];
    float* out = (float*)d_out;

    const int n_pairs = in_sizes[1] / PAIR_ELEMS;   // B * NJ from h
    const int pairs_per_block = WARPS_PER_BLOCK * CHUNK;
    const int blocks = (n_pairs + pairs_per_block - 1) / pairs_per_block;

    mse3d_kernel<<<blocks, BLOCK_THREADS>>>(o, h, t, v, out, n_pairs, blocks);
}

// round 16
// speedup vs baseline: 1.1393x; 1.1164x over previous
#include <cuda_runtime.h>
#include <cstdint>
#include <math.h>

#define COL 14
#define NJ 23
#define PAIR_ELEMS (COL * COL)   // 196
#define WARPS_PER_BLOCK 8
#define BLOCK_THREADS (WARPS_PER_BLOCK * 32)
#define CHUNK 10                 // 94208/(8*10) -> 1178 blocks ~ one wave

__device__ float        g_sum   = 0.0f;
__device__ unsigned int g_count = 0u;

// gaussian weights exp(-k^2/2)/sum, k=-4..4 (normalized in double, cast to f32)
__device__ __constant__ float c_w[9] = {
    0.000133832f, 0.00443186f, 0.05399111f, 0.24197140f, 0.39894345f,
    0.24197140f, 0.05399111f, 0.00443186f, 0.000133832f
};

__device__ __forceinline__ void amax_node(float& v, int& i, float vr, int ir) {
    if (vr > v) { v = vr; i = ir; }   // strict >: ties keep smaller index
}
__device__ __forceinline__ void prefetch_l1(const void* p) {
    asm volatile("prefetch.global.L1 [%0];" :: "l"(p));
}

__global__ __launch_bounds__(BLOCK_THREADS, 8)
void mse3d_kernel(const float* __restrict__ o,
                  const float* __restrict__ h,
                  const float* __restrict__ t,
                  const int*   __restrict__ v,
                  float* __restrict__ out,
                  int n_pairs, int nblocks) {
    __shared__ float sMt[PAIR_ELEMS];   // [i*COL+r] = M[r][i]
    __shared__ float sColMin[COL], sColMax[COL];
    __shared__ float sColS1[COL], sColS2[COL];
    __shared__ float wsum[WARPS_PER_BLOCK];

    const int tid = threadIdx.x;

    // ---- per-block gaussian matrix build ----
    if (tid < PAIR_ELEMS) {
        const int outr = tid / COL;
        const int i    = tid % COL;
        float m = 0.0f;
        #pragma unroll
        for (int k = -4; k <= 4; k++) {
            int ii = (outr + k + 2 * COL) % (2 * COL);
            if (ii >= COL) ii = 2 * COL - 1 - ii;
            if (ii == i) m += c_w[k + 4];
        }
        sMt[i * COL + outr] = m;
    }
    __syncthreads();
    if (tid < COL) {
        float mn = INFINITY, mx = -INFINITY, s1 = 0.0f, s2 = 0.0f;
        #pragma unroll
        for (int r = 0; r < COL; r++) {
            float val = sMt[tid * COL + r];   // M[r][tid]
            mn = fminf(mn, val);
            mx = fmaxf(mx, val);
            s1 += val;
            s2 = fmaf(val, val, s2);
        }
        sColMin[tid] = mn;
        sColMax[tid] = mx;
        sColS1[tid]  = s1;
        sColS2[tid]  = s2;
    }
    __syncthreads();

    const int lane  = tid & 31;
    const int warp  = tid >> 5;
    const int gwarp = blockIdx.x * WARPS_PER_BLOCK + warp;
    const int pair0 = gwarp * CHUNK;
    const int cnt   = min(CHUNK, n_pairs - pair0);

    float acc  = 0.0f;   // d1
    float acc2 = 0.0f;   // d2 + per-pair constant terms

    if (cnt > 0) {
        const bool hasb = (lane < 17);     // second float4 (idx 32+lane < 49)

        // per-lane element coordinates, loop-invariant
        const int ea = 4 * lane;
        const int ra0 = ea / COL, ca0 = ea - ra0 * COL;
        const int eb = 4 * (32 + lane);
        const int rb0 = eb / COL, cb0 = eb - rb0 * COL;

        const float4* hbase = (const float4*)(h + (size_t)pair0 * PAIR_ELEMS);

        // ---- per-chunk t/v load (coalesced) ----
        const float tl = (lane < 3 * cnt) ? t[(size_t)pair0 * 3 + lane] : 0.0f;
        const int   vl = (lane < cnt) ? v[(size_t)(pair0 + lane) * 2] : 0;

        // ---- pre-pass: lane m holds pair m's packed params ----
        // pparam = xc | yc<<4 | mask<<8 ; pinv = -2*inv ; pnb = -2*nb
        // the warp-uniform sum(tt^2) constant folds into acc2 here (once).
        int   pparam = 0;
        float pinv = 0.0f, pnb = 0.0f;
        {
            const int tli = (int)truncf(tl * (float)COL);
            const int xi = __shfl_sync(0xffffffffu, tli, (3 * lane) & 31);
            const int yi = __shfl_sync(0xffffffffu, tli, (3 * lane + 1) & 31);
            if (lane < cnt) {
                const bool in_range = (xi >= 0) && (xi <= COL - 1) &&
                                      (yi >= 0) && (yi <= COL - 1);
                const bool mask = (vl == 1) && in_range;
                const int xc = min(max(xi, 0), COL - 1);
                const int yc = min(max(yi, 0), COL - 1);
                pparam = xc | (yc << 4) | (mask ? (1 << 8) : 0);
                if (mask) {
                    const float mn  = sColMin[yc] * sColMin[xc];
                    const float mx  = sColMax[yc] * sColMax[xc];
                    const float inv = 1.0f / (mx - mn);
                    const float nb  = -mn * inv;
                    pinv = -2.0f * inv;
                    pnb  = -2.0f * nb;
                    const float S1 = sColS1[yc] * sColS1[xc];
                    const float S2 = sColS2[yc] * sColS2[xc];
                    float ct = inv * inv * S2;
                    ct = fmaf(2.0f * inv * nb, S1, ct);
                    ct = fmaf((float)PAIR_ELEMS * nb, nb, ct);
                    acc2 += ct;
                }
            }
        }

        // warm L1 for pair 0
        prefetch_l1(hbase + lane);
        if (hasb) prefetch_l1(hbase + 32 + lane);

        int myAmax = 0;   // lane k banks pair k's argmax

        // ================= Phase 1: h-only (d1 + argmax) =================
        for (int k = 0; k < cnt; k++) {
            const float4* hp = hbase + (size_t)k * 49;
            float4 va = hp[lane];
            float4 vb = hasb ? hp[32 + lane] : make_float4(0.f, 0.f, 0.f, 0.f);

            // prefetch next pair's tile into L1 (zero-register pipelining)
            if (k + 1 < cnt) {
                prefetch_l1(hp + 49 + lane);
                if (hasb) prefetch_l1(hp + 49 + 32 + lane);
            }

            // single packed-param broadcast per pair
            const int pp = __shfl_sync(0xffffffffu, pparam, k);

            // ---- tree argmax over the 8 local elements ----
            float m0 = va.x; int i0 = ea;
            amax_node(m0, i0, va.y, ea + 1);
            float m1 = va.z; int i1 = ea + 2;
            amax_node(m1, i1, va.w, ea + 3);
            float m2 = vb.x; int i2 = eb;
            amax_node(m2, i2, vb.y, eb + 1);
            float m3 = vb.z; int i3 = eb + 2;
            amax_node(m3, i3, vb.w, eb + 3);
            amax_node(m0, i0, m1, i1);
            amax_node(m2, i2, m3, i3);
            amax_node(m0, i0, m2, i2);
            // h >= 0: bits order-isomorphic; first occurrence via min-index
            const unsigned int bbits = __float_as_uint(m0);
            const unsigned int mbits = __reduce_max_sync(0xffffffffu, bbits);
            const int amax = (int)__reduce_min_sync(
                0xffffffffu, (bbits == mbits) ? (unsigned)i0 : 0xffffffffu);
            if (lane == k) myAmax = amax;

            // ---- always: sum h^2 ----
            acc = fmaf(va.x, va.x, acc);
            acc = fmaf(va.y, va.y, acc);
            acc = fmaf(va.z, va.z, acc);
            acc = fmaf(va.w, va.w, acc);
            acc = fmaf(vb.x, vb.x, acc);
            acc = fmaf(vb.y, vb.y, acc);
            acc = fmaf(vb.z, vb.z, acc);
            acc = fmaf(vb.w, vb.w, acc);

            // ---- masked path: cross term only (constants pre-folded) ----
            if (pp & (1 << 8)) {                      // warp-uniform branch
                const float ninv2 = __shfl_sync(0xffffffffu, pinv, k);
                const float nnb2  = __shfl_sync(0xffffffffu, pnb,  k);
                const int xc = pp & 15;
                const int yc = (pp >> 4) & 15;
                const float* gy = &sMt[yc * COL];
                const float* gx = &sMt[xc * COL];

                float hw = 0.0f, sh = 0.0f;
                {
                    int r = ra0, c = ca0;
                    float hv[4] = {va.x, va.y, va.z, va.w};
                    #pragma unroll
                    for (int q = 0; q < 4; q++) {
                        hw = fmaf(hv[q], gy[r] * gx[c], hw);
                        sh += hv[q];
                        if (++c == COL) { c = 0; ++r; }
                    }
                }
                if (hasb) {
                    int r = rb0, c = cb0;
                    float hv[4] = {vb.x, vb.y, vb.z, vb.w};
                    #pragma unroll
                    for (int q = 0; q < 4; q++) {
                        hw = fmaf(hv[q], gy[r] * gx[c], hw);
                        sh += hv[q];
                        if (++c == COL) { c = 0; ++r; }
                    }
                }
                acc = fmaf(ninv2, hw, acc);
                acc = fmaf(nnb2,  sh, acc);
            }
        }

        // ====== Phase 2: all o-gathers at once (up to 30 concurrent) ======
        {
            const int kq = min(lane / 3, cnt - 1);     // clamped for shfl
            const int am = __shfl_sync(0xffffffffu, myAmax, kq);
            if (lane < 3 * cnt) {
                const int k    = lane / 3;
                const int comp = lane - 3 * k;
                const int pair = pair0 + k;
                const int b    = pair / NJ;
                const int j    = pair - b * NJ;
                const int ayk  = am / COL;
                const int axk  = am - ayk * COL;
                const int row  = b * (3 * NJ) + j + comp * NJ;
                const float ov = __ldg(o + ((size_t)row * PAIR_ELEMS + am));
                const float scale = 1.0f / (float)COL;
                const float addv = (comp == 0) ? (float)axk * scale
                                 : ((comp == 1) ? (float)ayk * scale : 0.0f);
                const float d = ov + addv - tl;        // tl == t[pair*3+comp]
                acc2 = fmaf(d, d, acc2);
            }
        }
    }

    acc += acc2;

    // ---- block reduction ----
    #pragma unroll
    for (int off = 16; off > 0; off >>= 1)
        acc += __shfl_down_sync(0xffffffffu, acc, off);
    if (lane == 0) wsum[warp] = acc;
    __syncthreads();

    if (warp == 0) {
        float s = (lane < WARPS_PER_BLOCK) ? wsum[lane] : 0.0f;
        #pragma unroll
        for (int off = WARPS_PER_BLOCK / 2; off > 0; off >>= 1)
            s += __shfl_down_sync(0xffffffffu, s, off);
        if (lane == 0) {
            atomicAdd(&g_sum, s * (1.0f / (float)NJ));
            __threadfence();
            unsigned int done = atomicAdd(&g_count, 1u);
            if (done == (unsigned)nblocks - 1) {
                float total = atomicExch(&g_sum, 0.0f);
                out[0] = total;
                g_count = 0u;
                __threadfence();
            }
        }
    }
}

extern "C" void kernel_launch(void* const* d_in, const int* in_sizes, int n_in,
                              void* d_out, int out_size) {
    const float* o = (const float*)d_in[0];
    const float* h = (const float*)d_in[1];
    const float* t = (const float*)d_in[2];
    const int*   v = (const int*)d_in[3];
    float* out = (float*)d_out;

    const int n_pairs = in_sizes[1] / PAIR_ELEMS;   // B * NJ from h
    const int pairs_per_block = WARPS_PER_BLOCK * CHUNK;
    const int blocks = (n_pairs + pairs_per_block - 1) / pairs_per_block;

    mse3d_kernel<<<blocks, BLOCK_THREADS>>>(o, h, t, v, out, n_pairs, blocks);
}